// round 1
// baseline (speedup 1.0000x reference)
#include <cuda_runtime.h>
#include <cuda_bf16.h>
#include <math.h>

#define L 2048
#define C 256
#define NB 4
#define H 8
#define D 32
#define SD 16.0f

// ---------------- scratch (device globals; no allocation allowed) ----------------
__device__ float g_h [L*C];
__device__ float g_h1[L*C];
__device__ float g_q [L*C];
__device__ float g_k [L*C];
__device__ float g_v [L*C];
__device__ float g_ao[L*C];
__device__ float g_mid[L*4*C];
__device__ __nv_bfloat16 g_bias[(size_t)NB*H*L*L];   // 256 MB, [b*8+h][i*L+j]
__device__ float g_tc[C];
__device__ float g_ss1[NB][2*C];
__device__ float g_ss2[NB][2*C];
__device__ float g_scal[4];   // c_skip, c_out, c_in

__device__ __forceinline__ float gelu_exact(float x) {
    return 0.5f * x * (1.0f + erff(x * 0.70710678118654752f));
}

// ---------------- K0: time embedding, time MLP, adaLN cond projections ----------------
__global__ void __launch_bounds__(256) k_prep(
    const float* __restrict__ sigma,
    const float* __restrict__ tW1, const float* __restrict__ tb1,
    const float* __restrict__ tW2, const float* __restrict__ tb2,
    const float* __restrict__ a1pW, const float* __restrict__ a1pb,
    const float* __restrict__ a2pW, const float* __restrict__ a2pb)
{
    __shared__ float temb[C];
    __shared__ float hid[4*C];
    __shared__ float tcs[C];
    const int t = threadIdx.x;
    const float sg = sigma[0];
    if (t == 0) {
        float s2 = sg*sg + SD*SD;
        g_scal[0] = SD*SD / s2;          // c_skip
        g_scal[1] = sg*SD*rsqrtf(s2);    // c_out
        g_scal[2] = rsqrtf(s2);          // c_in
    }
    const float c_noise = 0.25f * logf(sg + 1e-8f);
    if (t < 128) {
        float fr = expf(-logf(10000.0f) * (float)t / 128.0f);
        float a = c_noise * fr;
        temb[t]       = cosf(a);
        temb[t + 128] = sinf(a);
    }
    __syncthreads();
    for (int r = t; r < 4*C; r += 256) {
        float acc = tb1[r];
        const float* w = tW1 + (size_t)r * C;
        for (int k2 = 0; k2 < C; k2++) acc += temb[k2] * w[k2];
        hid[r] = gelu_exact(acc);
    }
    __syncthreads();
    for (int r = t; r < C; r += 256) {
        float acc = tb2[r];
        const float* w = tW2 + (size_t)r * 4*C;
        for (int k2 = 0; k2 < 4*C; k2++) acc += hid[k2] * w[k2];
        tcs[r] = acc;
        g_tc[r] = acc;
    }
    __syncthreads();
    for (int idx = t; idx < NB*2*C; idx += 256) {
        int b = idx / (2*C), r = idx % (2*C);
        float acc1 = a1pb[b*2*C + r];
        const float* w1 = a1pW + ((size_t)b*2*C + r) * C;
        float acc2 = a2pb[b*2*C + r];
        const float* w2 = a2pW + ((size_t)b*2*C + r) * C;
        for (int k2 = 0; k2 < C; k2++) { acc1 += tcs[k2]*w1[k2]; acc2 += tcs[k2]*w2[k2]; }
        g_ss1[b][r] = acc1;
        g_ss2[b][r] = acc2;
    }
}

// ---------------- pair bias: [L*L,64] @ [64,32] -> bf16 ----------------
__global__ void __launch_bounds__(256) k_bias(const float* __restrict__ pair,
                                              const float* __restrict__ pW)
{
    __shared__ float ws[64][36];    // [k][o]
    __shared__ float As[64][132];   // [k][row-in-tile], 128 rows
    const int tid = threadIdx.x;
    for (int idx = tid; idx < 32*64; idx += 256) {
        int o = idx >> 6, k = idx & 63;
        ws[k][o] = pW[idx];         // pW[o*64+k]
    }
    const size_t row0 = (size_t)blockIdx.x * 128;
    for (int q = tid; q < 128*16; q += 256) {
        int r = q >> 4, c4 = q & 15;
        float4 v = *(const float4*)(pair + (row0 + r) * 64 + 4*c4);
        As[4*c4+0][r] = v.x; As[4*c4+1][r] = v.y;
        As[4*c4+2][r] = v.z; As[4*c4+3][r] = v.w;
    }
    __syncthreads();
    const int rx = tid & 31;    // row lane (coalesced bf16 writes)
    const int oc = tid >> 5;    // 0..7 -> 4 outputs each
    float acc[4][4] = {};
    #pragma unroll 16
    for (int k = 0; k < 64; k++) {
        float4 b4 = *(const float4*)&ws[k][4*oc];
        float a0 = As[k][rx], a1 = As[k][rx+32], a2 = As[k][rx+64], a3 = As[k][rx+96];
        acc[0][0] += a0*b4.x; acc[0][1] += a0*b4.y; acc[0][2] += a0*b4.z; acc[0][3] += a0*b4.w;
        acc[1][0] += a1*b4.x; acc[1][1] += a1*b4.y; acc[1][2] += a1*b4.z; acc[1][3] += a1*b4.w;
        acc[2][0] += a2*b4.x; acc[2][1] += a2*b4.y; acc[2][2] += a2*b4.z; acc[2][3] += a2*b4.w;
        acc[3][0] += a3*b4.x; acc[3][1] += a3*b4.y; acc[3][2] += a3*b4.z; acc[3][3] += a3*b4.w;
    }
    #pragma unroll
    for (int j = 0; j < 4; j++) {
        int o = 4*oc + j;
        size_t base = (size_t)o * (size_t)L * (size_t)L + row0;
        #pragma unroll
        for (int i = 0; i < 4; i++)
            g_bias[base + rx + 32*i] = __float2bfloat16(acc[i][j]);
    }
}

// ---------------- generic tiled SGEMM: C = A[M,K] @ B[N,K]^T (+bias)(gelu)(+res) ----------------
template<bool HAS_BIAS, bool DO_GELU, bool HAS_RES>
__global__ void __launch_bounds__(256) k_gemm(
    const float* __restrict__ A, const float* __restrict__ Bw,
    const float* __restrict__ bias, const float* __restrict__ Rsrc,
    float* __restrict__ Cout, int M, int N, int K)
{
    __shared__ float As[16][68];
    __shared__ float Bs[16][68];
    const int tid = threadIdx.x;
    const int tx = tid & 15, ty = tid >> 4;
    const int m0 = blockIdx.y * 64, n0 = blockIdx.x * 64;
    const int lr = tid >> 2, lc = tid & 3;
    float acc[4][4] = {};
    for (int k0 = 0; k0 < K; k0 += 16) {
        float4 av = *(const float4*)&A [(size_t)(m0 + lr) * K + k0 + 4*lc];
        float4 bv = *(const float4*)&Bw[(size_t)(n0 + lr) * K + k0 + 4*lc];
        As[4*lc+0][lr] = av.x; As[4*lc+1][lr] = av.y; As[4*lc+2][lr] = av.z; As[4*lc+3][lr] = av.w;
        Bs[4*lc+0][lr] = bv.x; Bs[4*lc+1][lr] = bv.y; Bs[4*lc+2][lr] = bv.z; Bs[4*lc+3][lr] = bv.w;
        __syncthreads();
        #pragma unroll
        for (int kk = 0; kk < 16; kk++) {
            float4 a = *(const float4*)&As[kk][4*ty];
            float4 b = *(const float4*)&Bs[kk][4*tx];
            acc[0][0]+=a.x*b.x; acc[0][1]+=a.x*b.y; acc[0][2]+=a.x*b.z; acc[0][3]+=a.x*b.w;
            acc[1][0]+=a.y*b.x; acc[1][1]+=a.y*b.y; acc[1][2]+=a.y*b.z; acc[1][3]+=a.y*b.w;
            acc[2][0]+=a.z*b.x; acc[2][1]+=a.z*b.y; acc[2][2]+=a.z*b.z; acc[2][3]+=a.z*b.w;
            acc[3][0]+=a.w*b.x; acc[3][1]+=a.w*b.y; acc[3][2]+=a.w*b.z; acc[3][3]+=a.w*b.w;
        }
        __syncthreads();
    }
    #pragma unroll
    for (int i = 0; i < 4; i++) {
        int row = m0 + 4*ty + i;
        #pragma unroll
        for (int j = 0; j < 4; j++) {
            int col = n0 + 4*tx + j;
            float v = acc[i][j];
            if (HAS_BIAS) v += bias[col];
            if (DO_GELU)  v = gelu_exact(v);
            if (HAS_RES)  v += Rsrc[(size_t)row * N + col];
            Cout[(size_t)row * N + col] = v;
        }
    }
}

// ---------------- coord path add: h += c_in * x @ coordW^T + coord_b ----------------
__global__ void __launch_bounds__(256) k_coord(const float* __restrict__ xn,
                                               const float* __restrict__ cW,
                                               const float* __restrict__ cb)
{
    int idx = blockIdx.x * 256 + threadIdx.x;
    int i = idx >> 8, c = idx & 255;
    float cin = g_scal[2];
    g_h[idx] += cb[c] + cin * (xn[i*3+0]*cW[c*3+0] + xn[i*3+1]*cW[c*3+1] + xn[i*3+2]*cW[c*3+2]);
}

// ---------------- adaLN: Y = LN(X)*g*(1+scale) + shift ----------------
__global__ void __launch_bounds__(256) k_adaln(const float* __restrict__ X, float* __restrict__ Y,
                                               const float* __restrict__ gw, const float* __restrict__ bw,
                                               int blk, int which)
{
    __shared__ float red[8];
    const int row = blockIdx.x, t = threadIdx.x;
    const float* ss = which ? g_ss2[blk] : g_ss1[blk];
    float x = X[(size_t)row * C + t];
    float v = x;
    #pragma unroll
    for (int off = 16; off; off >>= 1) v += __shfl_xor_sync(0xffffffffu, v, off);
    if ((t & 31) == 0) red[t >> 5] = v;
    __syncthreads();
    float mu = 0.f;
    #pragma unroll
    for (int w = 0; w < 8; w++) mu += red[w];
    mu *= (1.0f/256.0f);
    __syncthreads();
    float d = x - mu;
    v = d * d;
    #pragma unroll
    for (int off = 16; off; off >>= 1) v += __shfl_xor_sync(0xffffffffu, v, off);
    if ((t & 31) == 0) red[t >> 5] = v;
    __syncthreads();
    float var = 0.f;
    #pragma unroll
    for (int w = 0; w < 8; w++) var += red[w];
    var *= (1.0f/256.0f);
    float y = d * rsqrtf(var + 1e-5f) * gw[t] + bw[t];
    Y[(size_t)row * C + t] = y * (1.0f + ss[t]) + ss[C + t];
}

// ---------------- flash attention with precomputed bf16 bias ----------------
__global__ void __launch_bounds__(256) k_attn(int blk)
{
    const int h  = blockIdx.y;
    const int i0 = blockIdx.x * 64;
    const int tid = threadIdx.x;
    const int tx = tid & 15, ty = tid >> 4;
    __shared__ float Qs[32][68], Ks[32][68];
    __shared__ float Vs[64][34];
    __shared__ float Ps[64][68];
    const float scale = 0.17677669529663687f;  // 1/sqrt(32)

    for (int idx = tid; idx < 64*32; idx += 256) {
        int m = idx >> 5, d = idx & 31;
        Qs[d][m] = g_q[(size_t)(i0 + m) * C + h*32 + d] * scale;
    }
    float m_run[4], l_run[4], o[4][2];
    #pragma unroll
    for (int i = 0; i < 4; i++) { m_run[i] = -1e30f; l_run[i] = 0.f; o[i][0] = 0.f; o[i][1] = 0.f; }
    const __nv_bfloat16* bias = g_bias + ((size_t)blk * H + h) * (size_t)L * (size_t)L;

    for (int j0 = 0; j0 < L; j0 += 64) {
        for (int idx = tid; idx < 64*32; idx += 256) {
            int m = idx >> 5, d = idx & 31;
            Ks[d][m] = g_k[(size_t)(j0 + m) * C + h*32 + d];
            Vs[m][d] = g_v[(size_t)(j0 + m) * C + h*32 + d];
        }
        __syncthreads();
        float s[4][4] = {};
        #pragma unroll
        for (int d = 0; d < 32; d++) {
            float4 a = *(const float4*)&Qs[d][4*ty];
            float4 b = *(const float4*)&Ks[d][4*tx];
            s[0][0]+=a.x*b.x; s[0][1]+=a.x*b.y; s[0][2]+=a.x*b.z; s[0][3]+=a.x*b.w;
            s[1][0]+=a.y*b.x; s[1][1]+=a.y*b.y; s[1][2]+=a.y*b.z; s[1][3]+=a.y*b.w;
            s[2][0]+=a.z*b.x; s[2][1]+=a.z*b.y; s[2][2]+=a.z*b.z; s[2][3]+=a.z*b.w;
            s[3][0]+=a.w*b.x; s[3][1]+=a.w*b.y; s[3][2]+=a.w*b.z; s[3][3]+=a.w*b.w;
        }
        #pragma unroll
        for (int i = 0; i < 4; i++) {
            const __nv_bfloat16* bp = bias + (size_t)(i0 + 4*ty + i) * L + j0 + 4*tx;
            __nv_bfloat162 b01 = *(const __nv_bfloat162*)bp;
            __nv_bfloat162 b23 = *(const __nv_bfloat162*)(bp + 2);
            s[i][0] += __bfloat162float(b01.x); s[i][1] += __bfloat162float(b01.y);
            s[i][2] += __bfloat162float(b23.x); s[i][3] += __bfloat162float(b23.y);
        }
        float corr[4];
        #pragma unroll
        for (int i = 0; i < 4; i++) {
            float mx = fmaxf(fmaxf(s[i][0], s[i][1]), fmaxf(s[i][2], s[i][3]));
            #pragma unroll
            for (int off = 8; off; off >>= 1) mx = fmaxf(mx, __shfl_xor_sync(0xffffffffu, mx, off));
            float mnew = fmaxf(m_run[i], mx);
            float cfac = __expf(m_run[i] - mnew);
            float rs = 0.f;
            #pragma unroll
            for (int j = 0; j < 4; j++) { float p = __expf(s[i][j] - mnew); s[i][j] = p; rs += p; }
            #pragma unroll
            for (int off = 8; off; off >>= 1) rs += __shfl_xor_sync(0xffffffffu, rs, off);
            l_run[i] = l_run[i] * cfac + rs;
            m_run[i] = mnew;
            corr[i] = cfac;
        }
        #pragma unroll
        for (int i = 0; i < 4; i++)
            *(float4*)&Ps[4*ty + i][4*tx] = make_float4(s[i][0], s[i][1], s[i][2], s[i][3]);
        __syncthreads();
        #pragma unroll
        for (int i = 0; i < 4; i++) { o[i][0] *= corr[i]; o[i][1] *= corr[i]; }
        #pragma unroll 8
        for (int j = 0; j < 64; j++) {
            float2 v = *(const float2*)&Vs[j][2*tx];
            #pragma unroll
            for (int i = 0; i < 4; i++) {
                float p = Ps[4*ty + i][j];
                o[i][0] += p * v.x;
                o[i][1] += p * v.y;
            }
        }
        __syncthreads();
    }
    #pragma unroll
    for (int i = 0; i < 4; i++) {
        float inv = 1.0f / l_run[i];
        size_t base = (size_t)(i0 + 4*ty + i) * C + h*32 + 2*tx;
        g_ao[base + 0] = o[i][0] * inv;
        g_ao[base + 1] = o[i][1] * inv;
    }
}

// ---------------- final: out = c_skip*x + c_out*(h @ outW^T + b) ----------------
__global__ void __launch_bounds__(256) k_final(const float* __restrict__ xn,
                                               const float* __restrict__ oW,
                                               const float* __restrict__ ob,
                                               float* __restrict__ out)
{
    const int warp = threadIdx.x >> 5, lane = threadIdx.x & 31;
    const int row = blockIdx.x * 8 + warp;
    const float* hr = g_h + (size_t)row * C;
    #pragma unroll
    for (int c = 0; c < 3; c++) {
        float s = 0.f;
        for (int k = lane; k < C; k += 32) s += hr[k] * oW[c*C + k];
        #pragma unroll
        for (int off = 16; off; off >>= 1) s += __shfl_xor_sync(0xffffffffu, s, off);
        if (lane == 0)
            out[row*3 + c] = g_scal[0] * xn[row*3 + c] + g_scal[1] * (s + ob[c]);
    }
}

// ---------------- launcher ----------------
extern "C" void kernel_launch(void* const* d_in, const int* in_sizes, int n_in,
                              void* d_out, int out_size)
{
    const float* x_noisy  = (const float*)d_in[0];
    const float* sigma    = (const float*)d_in[1];
    const float* single   = (const float*)d_in[2];
    const float* pair     = (const float*)d_in[3];
    const float* coord_W  = (const float*)d_in[4];
    const float* coord_b  = (const float*)d_in[5];
    const float* single_W = (const float*)d_in[6];
    const float* single_b = (const float*)d_in[7];
    const float* tmlp_W1  = (const float*)d_in[8];
    const float* tmlp_b1  = (const float*)d_in[9];
    const float* tmlp_W2  = (const float*)d_in[10];
    const float* tmlp_b2  = (const float*)d_in[11];
    const float* ada1_g   = (const float*)d_in[12];
    const float* ada1_b   = (const float*)d_in[13];
    const float* ada1_pW  = (const float*)d_in[14];
    const float* ada1_pb  = (const float*)d_in[15];
    const float* qW       = (const float*)d_in[16];
    const float* kW       = (const float*)d_in[17];
    const float* vW       = (const float*)d_in[18];
    const float* pairW    = (const float*)d_in[19];
    const float* outW     = (const float*)d_in[20];
    const float* outb     = (const float*)d_in[21];
    const float* ada2_g   = (const float*)d_in[22];
    const float* ada2_b   = (const float*)d_in[23];
    const float* ada2_pW  = (const float*)d_in[24];
    const float* ada2_pb  = (const float*)d_in[25];
    const float* ffn_W1   = (const float*)d_in[26];
    const float* ffn_b1   = (const float*)d_in[27];
    const float* ffn_W2   = (const float*)d_in[28];
    const float* ffn_b2   = (const float*)d_in[29];
    const float* out_W    = (const float*)d_in[30];
    const float* out_b    = (const float*)d_in[31];
    float* out = (float*)d_out;

    float *p_h, *p_h1, *p_q, *p_k, *p_v, *p_ao, *p_mid;
    cudaGetSymbolAddress((void**)&p_h,  g_h);
    cudaGetSymbolAddress((void**)&p_h1, g_h1);
    cudaGetSymbolAddress((void**)&p_q,  g_q);
    cudaGetSymbolAddress((void**)&p_k,  g_k);
    cudaGetSymbolAddress((void**)&p_v,  g_v);
    cudaGetSymbolAddress((void**)&p_ao, g_ao);
    cudaGetSymbolAddress((void**)&p_mid, g_mid);

    k_prep<<<1, 256>>>(sigma, tmlp_W1, tmlp_b1, tmlp_W2, tmlp_b2,
                       ada1_pW, ada1_pb, ada2_pW, ada2_pb);
    k_bias<<<(L*L)/128, 256>>>(pair, pairW);
    k_gemm<true,false,false><<<dim3(C/64, L/64), 256>>>(single, single_W, single_b, nullptr, p_h, L, C, C);
    k_coord<<<L, 256>>>(x_noisy, coord_W, coord_b);

    for (int b = 0; b < NB; b++) {
        k_adaln<<<L, 256>>>(p_h, p_h1, ada1_g + b*C, ada1_b + b*C, b, 0);
        k_gemm<false,false,false><<<dim3(C/64, L/64), 256>>>(p_h1, qW + (size_t)b*C*C, nullptr, nullptr, p_q, L, C, C);
        k_gemm<false,false,false><<<dim3(C/64, L/64), 256>>>(p_h1, kW + (size_t)b*C*C, nullptr, nullptr, p_k, L, C, C);
        k_gemm<false,false,false><<<dim3(C/64, L/64), 256>>>(p_h1, vW + (size_t)b*C*C, nullptr, nullptr, p_v, L, C, C);
        k_attn<<<dim3(L/64, H), 256>>>(b);
        k_gemm<true,false,true><<<dim3(C/64, L/64), 256>>>(p_ao, outW + (size_t)b*C*C, outb + b*C, p_h, p_h, L, C, C);
        k_adaln<<<L, 256>>>(p_h, p_h1, ada2_g + b*C, ada2_b + b*C, b, 1);
        k_gemm<true,true,false><<<dim3(4*C/64, L/64), 256>>>(p_h1, ffn_W1 + (size_t)b*4*C*C, ffn_b1 + b*4*C, nullptr, p_mid, L, 4*C, C);
        k_gemm<true,false,true><<<dim3(C/64, L/64), 256>>>(p_mid, ffn_W2 + (size_t)b*4*C*C, ffn_b2 + b*C, p_h, p_h, L, C, 4*C);
    }
    k_final<<<L/8, 256>>>(x_noisy, out_W, out_b, out);
}

// round 2
// speedup vs baseline: 1.0010x; 1.0010x over previous
#include <cuda_runtime.h>
#include <cuda_bf16.h>
#include <math.h>

#define L 2048
#define C 256
#define NB 4
#define H 8
#define D 32
#define SD 16.0f

// ---------------- scratch (device globals; no allocation allowed) ----------------
__device__ float g_h [L*C];
__device__ float g_h1[L*C];
__device__ float g_q [L*C];
__device__ float g_k [L*C];
__device__ float g_v [L*C];
__device__ float g_ao[L*C];
__device__ float g_mid[L*4*C];
__device__ __nv_bfloat16 g_bias[(size_t)NB*H*L*L];   // 256 MB, [b*8+h][i*L+j]
__device__ float g_tc[C];
__device__ float g_ss1[NB][2*C];
__device__ float g_ss2[NB][2*C];
__device__ float g_scal[4];   // c_skip, c_out, c_in

__device__ __forceinline__ float gelu_exact(float x) {
    return 0.5f * x * (1.0f + erff(x * 0.70710678118654752f));
}

// ---------------- K0: time embedding, time MLP, adaLN cond projections ----------------
__global__ void __launch_bounds__(256) k_prep(
    const float* __restrict__ sigma,
    const float* __restrict__ tW1, const float* __restrict__ tb1,
    const float* __restrict__ tW2, const float* __restrict__ tb2,
    const float* __restrict__ a1pW, const float* __restrict__ a1pb,
    const float* __restrict__ a2pW, const float* __restrict__ a2pb)
{
    __shared__ float temb[C];
    __shared__ float hid[4*C];
    __shared__ float tcs[C];
    const int t = threadIdx.x;
    const float sg = sigma[0];
    if (t == 0) {
        float s2 = sg*sg + SD*SD;
        g_scal[0] = SD*SD / s2;          // c_skip
        g_scal[1] = sg*SD*rsqrtf(s2);    // c_out
        g_scal[2] = rsqrtf(s2);          // c_in
    }
    const float c_noise = 0.25f * logf(sg + 1e-8f);
    if (t < 128) {
        float fr = expf(-logf(10000.0f) * (float)t / 128.0f);
        float a = c_noise * fr;
        temb[t]       = cosf(a);
        temb[t + 128] = sinf(a);
    }
    __syncthreads();
    for (int r = t; r < 4*C; r += 256) {
        float acc = tb1[r];
        const float* w = tW1 + (size_t)r * C;
        for (int k2 = 0; k2 < C; k2++) acc += temb[k2] * w[k2];
        hid[r] = gelu_exact(acc);
    }
    __syncthreads();
    for (int r = t; r < C; r += 256) {
        float acc = tb2[r];
        const float* w = tW2 + (size_t)r * 4*C;
        for (int k2 = 0; k2 < 4*C; k2++) acc += hid[k2] * w[k2];
        tcs[r] = acc;
        g_tc[r] = acc;
    }
    __syncthreads();
    for (int idx = t; idx < NB*2*C; idx += 256) {
        int b = idx / (2*C), r = idx % (2*C);
        float acc1 = a1pb[b*2*C + r];
        const float* w1 = a1pW + ((size_t)b*2*C + r) * C;
        float acc2 = a2pb[b*2*C + r];
        const float* w2 = a2pW + ((size_t)b*2*C + r) * C;
        for (int k2 = 0; k2 < C; k2++) { acc1 += tcs[k2]*w1[k2]; acc2 += tcs[k2]*w2[k2]; }
        g_ss1[b][r] = acc1;
        g_ss2[b][r] = acc2;
    }
}

// ---------------- pair bias: [L*L,64] @ [64,32] -> bf16 ----------------
__global__ void __launch_bounds__(256) k_bias(const float* __restrict__ pair,
                                              const float* __restrict__ pW)
{
    __shared__ float ws[64][36];    // [k][o]
    __shared__ float As[64][132];   // [k][row-in-tile], 128 rows
    const int tid = threadIdx.x;
    for (int idx = tid; idx < 32*64; idx += 256) {
        int o = idx >> 6, k = idx & 63;
        ws[k][o] = pW[idx];         // pW[o*64+k]
    }
    const size_t row0 = (size_t)blockIdx.x * 128;
    for (int q = tid; q < 128*16; q += 256) {
        int r = q >> 4, c4 = q & 15;
        float4 v = *(const float4*)(pair + (row0 + r) * 64 + 4*c4);
        As[4*c4+0][r] = v.x; As[4*c4+1][r] = v.y;
        As[4*c4+2][r] = v.z; As[4*c4+3][r] = v.w;
    }
    __syncthreads();
    const int rx = tid & 31;    // row lane (coalesced bf16 writes)
    const int oc = tid >> 5;    // 0..7 -> 4 outputs each
    float acc[4][4] = {};
    #pragma unroll 16
    for (int k = 0; k < 64; k++) {
        float4 b4 = *(const float4*)&ws[k][4*oc];
        float a0 = As[k][rx], a1 = As[k][rx+32], a2 = As[k][rx+64], a3 = As[k][rx+96];
        acc[0][0] += a0*b4.x; acc[0][1] += a0*b4.y; acc[0][2] += a0*b4.z; acc[0][3] += a0*b4.w;
        acc[1][0] += a1*b4.x; acc[1][1] += a1*b4.y; acc[1][2] += a1*b4.z; acc[1][3] += a1*b4.w;
        acc[2][0] += a2*b4.x; acc[2][1] += a2*b4.y; acc[2][2] += a2*b4.z; acc[2][3] += a2*b4.w;
        acc[3][0] += a3*b4.x; acc[3][1] += a3*b4.y; acc[3][2] += a3*b4.z; acc[3][3] += a3*b4.w;
    }
    #pragma unroll
    for (int j = 0; j < 4; j++) {
        int o = 4*oc + j;
        size_t base = (size_t)o * (size_t)L * (size_t)L + row0;
        #pragma unroll
        for (int i = 0; i < 4; i++)
            g_bias[base + rx + 32*i] = __float2bfloat16(acc[i][j]);
    }
}

// ---------------- generic tiled SGEMM: C = A[M,K] @ B[N,K]^T (+bias)(gelu)(+res) ----------------
template<bool HAS_BIAS, bool DO_GELU, bool HAS_RES>
__global__ void __launch_bounds__(256) k_gemm(
    const float* __restrict__ A, const float* __restrict__ Bw,
    const float* __restrict__ bias, const float* __restrict__ Rsrc,
    float* __restrict__ Cout, int M, int N, int K)
{
    __shared__ float As[16][68];
    __shared__ float Bs[16][68];
    const int tid = threadIdx.x;
    const int tx = tid & 15, ty = tid >> 4;
    const int m0 = blockIdx.y * 64, n0 = blockIdx.x * 64;
    const int lr = tid >> 2, lc = tid & 3;
    float acc[4][4] = {};
    for (int k0 = 0; k0 < K; k0 += 16) {
        float4 av = *(const float4*)&A [(size_t)(m0 + lr) * K + k0 + 4*lc];
        float4 bv = *(const float4*)&Bw[(size_t)(n0 + lr) * K + k0 + 4*lc];
        As[4*lc+0][lr] = av.x; As[4*lc+1][lr] = av.y; As[4*lc+2][lr] = av.z; As[4*lc+3][lr] = av.w;
        Bs[4*lc+0][lr] = bv.x; Bs[4*lc+1][lr] = bv.y; Bs[4*lc+2][lr] = bv.z; Bs[4*lc+3][lr] = bv.w;
        __syncthreads();
        #pragma unroll
        for (int kk = 0; kk < 16; kk++) {
            float4 a = *(const float4*)&As[kk][4*ty];
            float4 b = *(const float4*)&Bs[kk][4*tx];
            acc[0][0]+=a.x*b.x; acc[0][1]+=a.x*b.y; acc[0][2]+=a.x*b.z; acc[0][3]+=a.x*b.w;
            acc[1][0]+=a.y*b.x; acc[1][1]+=a.y*b.y; acc[1][2]+=a.y*b.z; acc[1][3]+=a.y*b.w;
            acc[2][0]+=a.z*b.x; acc[2][1]+=a.z*b.y; acc[2][2]+=a.z*b.z; acc[2][3]+=a.z*b.w;
            acc[3][0]+=a.w*b.x; acc[3][1]+=a.w*b.y; acc[3][2]+=a.w*b.z; acc[3][3]+=a.w*b.w;
        }
        __syncthreads();
    }
    #pragma unroll
    for (int i = 0; i < 4; i++) {
        int row = m0 + 4*ty + i;
        #pragma unroll
        for (int j = 0; j < 4; j++) {
            int col = n0 + 4*tx + j;
            float v = acc[i][j];
            if (HAS_BIAS) v += bias[col];
            if (DO_GELU)  v = gelu_exact(v);
            if (HAS_RES)  v += Rsrc[(size_t)row * N + col];
            Cout[(size_t)row * N + col] = v;
        }
    }
}

// ---------------- coord path add: h += c_in * x @ coordW^T + coord_b ----------------
__global__ void __launch_bounds__(256) k_coord(const float* __restrict__ xn,
                                               const float* __restrict__ cW,
                                               const float* __restrict__ cb)
{
    int idx = blockIdx.x * 256 + threadIdx.x;
    int i = idx >> 8, c = idx & 255;
    float cin = g_scal[2];
    g_h[idx] += cb[c] + cin * (xn[i*3+0]*cW[c*3+0] + xn[i*3+1]*cW[c*3+1] + xn[i*3+2]*cW[c*3+2]);
}

// ---------------- adaLN: Y = LN(X)*g*(1+scale) + shift ----------------
__global__ void __launch_bounds__(256) k_adaln(const float* __restrict__ X, float* __restrict__ Y,
                                               const float* __restrict__ gw, const float* __restrict__ bw,
                                               int blk, int which)
{
    __shared__ float red[8];
    const int row = blockIdx.x, t = threadIdx.x;
    const float* ss = which ? g_ss2[blk] : g_ss1[blk];
    float x = X[(size_t)row * C + t];
    float v = x;
    #pragma unroll
    for (int off = 16; off; off >>= 1) v += __shfl_xor_sync(0xffffffffu, v, off);
    if ((t & 31) == 0) red[t >> 5] = v;
    __syncthreads();
    float mu = 0.f;
    #pragma unroll
    for (int w = 0; w < 8; w++) mu += red[w];
    mu *= (1.0f/256.0f);
    __syncthreads();
    float d = x - mu;
    v = d * d;
    #pragma unroll
    for (int off = 16; off; off >>= 1) v += __shfl_xor_sync(0xffffffffu, v, off);
    if ((t & 31) == 0) red[t >> 5] = v;
    __syncthreads();
    float var = 0.f;
    #pragma unroll
    for (int w = 0; w < 8; w++) var += red[w];
    var *= (1.0f/256.0f);
    float y = d * rsqrtf(var + 1e-5f) * gw[t] + bw[t];
    Y[(size_t)row * C + t] = y * (1.0f + ss[t]) + ss[C + t];
}

// ---------------- flash attention with precomputed bf16 bias ----------------
__global__ void __launch_bounds__(256) k_attn(int blk)
{
    const int h  = blockIdx.y;
    const int i0 = blockIdx.x * 64;
    const int tid = threadIdx.x;
    const int tx = tid & 15, ty = tid >> 4;
    __shared__ float Qs[32][68], Ks[32][68];
    __shared__ float Vs[64][34];
    __shared__ float Ps[64][68];
    const float scale = 0.17677669529663687f;  // 1/sqrt(32)

    for (int idx = tid; idx < 64*32; idx += 256) {
        int m = idx >> 5, d = idx & 31;
        Qs[d][m] = g_q[(size_t)(i0 + m) * C + h*32 + d] * scale;
    }
    float m_run[4], l_run[4], o[4][2];
    #pragma unroll
    for (int i = 0; i < 4; i++) { m_run[i] = -1e30f; l_run[i] = 0.f; o[i][0] = 0.f; o[i][1] = 0.f; }
    const __nv_bfloat16* bias = g_bias + ((size_t)blk * H + h) * (size_t)L * (size_t)L;

    for (int j0 = 0; j0 < L; j0 += 64) {
        for (int idx = tid; idx < 64*32; idx += 256) {
            int m = idx >> 5, d = idx & 31;
            Ks[d][m] = g_k[(size_t)(j0 + m) * C + h*32 + d];
            Vs[m][d] = g_v[(size_t)(j0 + m) * C + h*32 + d];
        }
        __syncthreads();
        float s[4][4] = {};
        #pragma unroll
        for (int d = 0; d < 32; d++) {
            float4 a = *(const float4*)&Qs[d][4*ty];
            float4 b = *(const float4*)&Ks[d][4*tx];
            s[0][0]+=a.x*b.x; s[0][1]+=a.x*b.y; s[0][2]+=a.x*b.z; s[0][3]+=a.x*b.w;
            s[1][0]+=a.y*b.x; s[1][1]+=a.y*b.y; s[1][2]+=a.y*b.z; s[1][3]+=a.y*b.w;
            s[2][0]+=a.z*b.x; s[2][1]+=a.z*b.y; s[2][2]+=a.z*b.z; s[2][3]+=a.z*b.w;
            s[3][0]+=a.w*b.x; s[3][1]+=a.w*b.y; s[3][2]+=a.w*b.z; s[3][3]+=a.w*b.w;
        }
        #pragma unroll
        for (int i = 0; i < 4; i++) {
            const __nv_bfloat16* bp = bias + (size_t)(i0 + 4*ty + i) * L + j0 + 4*tx;
            __nv_bfloat162 b01 = *(const __nv_bfloat162*)bp;
            __nv_bfloat162 b23 = *(const __nv_bfloat162*)(bp + 2);
            s[i][0] += __bfloat162float(b01.x); s[i][1] += __bfloat162float(b01.y);
            s[i][2] += __bfloat162float(b23.x); s[i][3] += __bfloat162float(b23.y);
        }
        float corr[4];
        #pragma unroll
        for (int i = 0; i < 4; i++) {
            float mx = fmaxf(fmaxf(s[i][0], s[i][1]), fmaxf(s[i][2], s[i][3]));
            #pragma unroll
            for (int off = 8; off; off >>= 1) mx = fmaxf(mx, __shfl_xor_sync(0xffffffffu, mx, off));
            float mnew = fmaxf(m_run[i], mx);
            float cfac = __expf(m_run[i] - mnew);
            float rs = 0.f;
            #pragma unroll
            for (int j = 0; j < 4; j++) { float p = __expf(s[i][j] - mnew); s[i][j] = p; rs += p; }
            #pragma unroll
            for (int off = 8; off; off >>= 1) rs += __shfl_xor_sync(0xffffffffu, rs, off);
            l_run[i] = l_run[i] * cfac + rs;
            m_run[i] = mnew;
            corr[i] = cfac;
        }
        #pragma unroll
        for (int i = 0; i < 4; i++)
            *(float4*)&Ps[4*ty + i][4*tx] = make_float4(s[i][0], s[i][1], s[i][2], s[i][3]);
        __syncthreads();
        #pragma unroll
        for (int i = 0; i < 4; i++) { o[i][0] *= corr[i]; o[i][1] *= corr[i]; }
        #pragma unroll 8
        for (int j = 0; j < 64; j++) {
            float2 v = *(const float2*)&Vs[j][2*tx];
            #pragma unroll
            for (int i = 0; i < 4; i++) {
                float p = Ps[4*ty + i][j];
                o[i][0] += p * v.x;
                o[i][1] += p * v.y;
            }
        }
        __syncthreads();
    }
    #pragma unroll
    for (int i = 0; i < 4; i++) {
        float inv = 1.0f / l_run[i];
        size_t base = (size_t)(i0 + 4*ty + i) * C + h*32 + 2*tx;
        g_ao[base + 0] = o[i][0] * inv;
        g_ao[base + 1] = o[i][1] * inv;
    }
}

// ---------------- final: out = c_skip*x + c_out*(h @ outW^T + b) ----------------
__global__ void __launch_bounds__(256) k_final(const float* __restrict__ xn,
                                               const float* __restrict__ oW,
                                               const float* __restrict__ ob,
                                               float* __restrict__ out)
{
    const int warp = threadIdx.x >> 5, lane = threadIdx.x & 31;
    const int row = blockIdx.x * 8 + warp;
    const float* hr = g_h + (size_t)row * C;
    #pragma unroll
    for (int c = 0; c < 3; c++) {
        float s = 0.f;
        for (int k = lane; k < C; k += 32) s += hr[k] * oW[c*C + k];
        #pragma unroll
        for (int off = 16; off; off >>= 1) s += __shfl_xor_sync(0xffffffffu, s, off);
        if (lane == 0)
            out[row*3 + c] = g_scal[0] * xn[row*3 + c] + g_scal[1] * (s + ob[c]);
    }
}

// ---------------- launcher ----------------
extern "C" void kernel_launch(void* const* d_in, const int* in_sizes, int n_in,
                              void* d_out, int out_size)
{
    const float* x_noisy  = (const float*)d_in[0];
    const float* sigma    = (const float*)d_in[1];
    const float* single   = (const float*)d_in[2];
    const float* pair     = (const float*)d_in[3];
    const float* coord_W  = (const float*)d_in[4];
    const float* coord_b  = (const float*)d_in[5];
    const float* single_W = (const float*)d_in[6];
    const float* single_b = (const float*)d_in[7];
    const float* tmlp_W1  = (const float*)d_in[8];
    const float* tmlp_b1  = (const float*)d_in[9];
    const float* tmlp_W2  = (const float*)d_in[10];
    const float* tmlp_b2  = (const float*)d_in[11];
    const float* ada1_g   = (const float*)d_in[12];
    const float* ada1_b   = (const float*)d_in[13];
    const float* ada1_pW  = (const float*)d_in[14];
    const float* ada1_pb  = (const float*)d_in[15];
    const float* qW       = (const float*)d_in[16];
    const float* kW       = (const float*)d_in[17];
    const float* vW       = (const float*)d_in[18];
    const float* pairW    = (const float*)d_in[19];
    const float* outW     = (const float*)d_in[20];
    const float* outb     = (const float*)d_in[21];
    const float* ada2_g   = (const float*)d_in[22];
    const float* ada2_b   = (const float*)d_in[23];
    const float* ada2_pW  = (const float*)d_in[24];
    const float* ada2_pb  = (const float*)d_in[25];
    const float* ffn_W1   = (const float*)d_in[26];
    const float* ffn_b1   = (const float*)d_in[27];
    const float* ffn_W2   = (const float*)d_in[28];
    const float* ffn_b2   = (const float*)d_in[29];
    const float* out_W    = (const float*)d_in[30];
    const float* out_b    = (const float*)d_in[31];
    float* out = (float*)d_out;

    float *p_h, *p_h1, *p_q, *p_k, *p_v, *p_ao, *p_mid;
    cudaGetSymbolAddress((void**)&p_h,  g_h);
    cudaGetSymbolAddress((void**)&p_h1, g_h1);
    cudaGetSymbolAddress((void**)&p_q,  g_q);
    cudaGetSymbolAddress((void**)&p_k,  g_k);
    cudaGetSymbolAddress((void**)&p_v,  g_v);
    cudaGetSymbolAddress((void**)&p_ao, g_ao);
    cudaGetSymbolAddress((void**)&p_mid, g_mid);

    k_prep<<<1, 256>>>(sigma, tmlp_W1, tmlp_b1, tmlp_W2, tmlp_b2,
                       ada1_pW, ada1_pb, ada2_pW, ada2_pb);
    k_bias<<<(L*L)/128, 256>>>(pair, pairW);
    k_gemm<true,false,false><<<dim3(C/64, L/64), 256>>>(single, single_W, single_b, nullptr, p_h, L, C, C);
    k_coord<<<L, 256>>>(x_noisy, coord_W, coord_b);

    for (int b = 0; b < NB; b++) {
        k_adaln<<<L, 256>>>(p_h, p_h1, ada1_g + b*C, ada1_b + b*C, b, 0);
        k_gemm<false,false,false><<<dim3(C/64, L/64), 256>>>(p_h1, qW + (size_t)b*C*C, nullptr, nullptr, p_q, L, C, C);
        k_gemm<false,false,false><<<dim3(C/64, L/64), 256>>>(p_h1, kW + (size_t)b*C*C, nullptr, nullptr, p_k, L, C, C);
        k_gemm<false,false,false><<<dim3(C/64, L/64), 256>>>(p_h1, vW + (size_t)b*C*C, nullptr, nullptr, p_v, L, C, C);
        k_attn<<<dim3(L/64, H), 256>>>(b);
        k_gemm<true,false,true><<<dim3(C/64, L/64), 256>>>(p_ao, outW + (size_t)b*C*C, outb + b*C, p_h, p_h, L, C, C);
        k_adaln<<<L, 256>>>(p_h, p_h1, ada2_g + b*C, ada2_b + b*C, b, 1);
        k_gemm<true,true,false><<<dim3(4*C/64, L/64), 256>>>(p_h1, ffn_W1 + (size_t)b*4*C*C, ffn_b1 + b*4*C, nullptr, p_mid, L, 4*C, C);
        k_gemm<true,false,true><<<dim3(C/64, L/64), 256>>>(p_mid, ffn_W2 + (size_t)b*4*C*C, ffn_b2 + b*C, p_h, p_h, L, C, 4*C);
    }
    k_final<<<L/8, 256>>>(x_noisy, out_W, out_b, out);
}